// round 13
// baseline (speedup 1.0000x reference)
#include <cuda_runtime.h>

// lut_kernel_49538152792187 — 6-bit soft-LUT layer.
// x: [16, 2, 1024, 384] f32   out: [16, 2, 1024, 64] f32
// w: [1024, 64, 64]     f32
//
// FOUR threads per (out, lut): each owns a 16-entry subtree (tree levels
// 0-3; levels 0+1 folded into a bilinear table: 4 groups x {c0..c3}).
// Levels 4,5 combined via two shfl_xor blends; lane (g&3)==0 stores.
// 262144 threads = 8192 warps (~55/SM) — TLP is the empirically validated
// lever (occ 19->36% gave issue 47->52%). w read exactly once (disjoint
// 64B chunks, coalesced); x deduped via 4-lane broadcast.

#define BR 32

__device__ __forceinline__ float sig2(float v) {
    // (tanh(v)+1)/2 == 1/(1+exp(-2v)); randn v -> bounded, no overflow.
    float e = __expf(-2.0f * v);
    return __fdividef(1.0f, 1.0f + e);
}

__global__ void __launch_bounds__(128, 11)
lut_kernel(const float* __restrict__ x, const float* __restrict__ w,
           float* __restrict__ out) {
    const int g   = blockIdx.x * 128 + threadIdx.x;  // 0..262143
    const int sub = g & 3;                           // subtree index (= lane&3)
    const int ol  = g >> 2;                          // o*64 + lut, 0..65535
    const int lut = ol & 63;
    const int o   = ol >> 6;

    // ---- load 16-entry subtree, wq = sigmoid(2w), fold levels 0+1 ----
    const float4* wp = reinterpret_cast<const float4*>(
        w + (size_t)ol * 64 + sub * 16);
    float c0[4], c1[4], c2[4], c3[4];
#pragma unroll
    for (int m = 0; m < 4; m++) {
        float4 v = wp[m];
        float q0 = sig2(v.x), q1 = sig2(v.y), q2 = sig2(v.z), q3 = sig2(v.w);
        c0[m] = q0;
        c1[m] = q1 - q0;
        c2[m] = q2 - q0;
        c3[m] = ((q3 - q2) - q1) + q0;
    }

    const float* xp = x + (size_t)o * 384 + lut * 6;  // 8B-aligned
    float*       op = out + (size_t)ol;
    const size_t xs = (size_t)1024 * 384;
    const size_t os = (size_t)1024 * 64;

    // depth-1 prefetch (depth-2 measured neutral in R10)
    float2 a0 = *reinterpret_cast<const float2*>(xp);
    float2 a1 = *reinterpret_cast<const float2*>(xp + 2);
    float2 a2 = *reinterpret_cast<const float2*>(xp + 4);
    xp += xs;

#pragma unroll 4
    for (int br = 0; br < BR; br++) {
        const float B0 = a0.x, B1 = a0.y, B2 = a1.x,
                    B3 = a1.y, B4 = a2.x, B5 = a2.y;
        if (br + 1 < BR) {                 // prefetch next replica's bits
            a0 = *reinterpret_cast<const float2*>(xp);
            a1 = *reinterpret_cast<const float2*>(xp + 2);
            a2 = *reinterpret_cast<const float2*>(xp + 4);
            xp += xs;
        }

        // levels 0+1 via bilinear table: 4 groups
        const float t01 = B0 * B1;
        float y0 = fmaf(t01, c3[0], fmaf(B1, c2[0], fmaf(B0, c1[0], c0[0])));
        float y1 = fmaf(t01, c3[1], fmaf(B1, c2[1], fmaf(B0, c1[1], c0[1])));
        float y2 = fmaf(t01, c3[2], fmaf(B1, c2[2], fmaf(B0, c1[2], c0[2])));
        float y3 = fmaf(t01, c3[3], fmaf(B1, c2[3], fmaf(B0, c1[3], c0[3])));
        // level 2
        float z0 = fmaf(B2, y1 - y0, y0);
        float z1 = fmaf(B2, y3 - y2, y2);
        // level 3: this 16-entry subtree's value
        float v = fmaf(B3, z1 - z0, z0);

        // level 4: combine subtrees (0,1) and (2,3) — valid on lanes with
        // (sub&1)==0; other lanes compute a defined-but-unused value.
        float v1 = __shfl_xor_sync(0xffffffffu, v, 1);
        float r4 = fmaf(B4, v1 - v, v);
        // level 5: combine quad halves — valid on lanes with sub==0.
        float r4h = __shfl_xor_sync(0xffffffffu, r4, 2);
        float r5 = fmaf(B5, r4h - r4, r4);

        if (sub == 0) *op = r5;
        op += os;
    }
}

extern "C" void kernel_launch(void* const* d_in, const int* in_sizes, int n_in,
                              void* d_out, int out_size) {
    const float* x = (const float*)d_in[0];
    const float* w = (const float*)d_in[1];
    float* out = (float*)d_out;
    lut_kernel<<<2048, 128>>>(x, w, out);
}